// round 16
// baseline (speedup 1.0000x reference)
#include <cuda_runtime.h>

#define M_DIM 1000
#define N_DIM 100000
#define NPB 1024            // n per block: 256 threads * 4
#define MC_MAX 167          // max m per block (grid.y = 6)
#define M_RESIDENT 120      // rows m < 120 (48 MB) -> L2 evict_last resident

__device__ __forceinline__ unsigned long long pk2(float lo, float hi) {
    unsigned long long r;
    asm("mov.b64 %0, {%1, %2};" : "=l"(r) : "f"(lo), "f"(hi));
    return r;
}

__device__ __forceinline__ void fma2(unsigned long long& d,
                                     unsigned long long a,
                                     unsigned long long b,
                                     unsigned long long c) {
    asm("fma.rn.f32x2 %0, %1, %2, %3;" : "=l"(d) : "l"(a), "l"(b), "l"(c));
}

// streaming store (evict-first)
__device__ __forceinline__ void stcs4(float* p, unsigned long long a,
                                      unsigned long long b) {
    float x, y, z, w;
    asm("mov.b64 {%0, %1}, %2;" : "=f"(x), "=f"(y) : "l"(a));
    asm("mov.b64 {%0, %1}, %2;" : "=f"(z), "=f"(w) : "l"(b));
    asm volatile("st.global.cs.v4.f32 [%0], {%1, %2, %3, %4};"
                 :: "l"(p), "f"(x), "f"(y), "f"(z), "f"(w) : "memory");
}

// evict_last-hinted store (L2-resident candidate)
__device__ __forceinline__ void stel4(float* p, unsigned long long a,
                                      unsigned long long b,
                                      unsigned long long pol) {
    float x, y, z, w;
    asm("mov.b64 {%0, %1}, %2;" : "=f"(x), "=f"(y) : "l"(a));
    asm("mov.b64 {%0, %1}, %2;" : "=f"(z), "=f"(w) : "l"(b));
    asm volatile("st.global.L2::cache_hint.v4.f32 [%0], {%1, %2, %3, %4}, %5;"
                 :: "l"(p), "f"(x), "f"(y), "f"(z), "f"(w), "l"(pol)
                 : "memory");
}

// ---------------------------------------------------------------------------
// Fused kernel: out[m*N + n] = sum_k Z[k][m] * W[k][n]
// grid (98,6) = 588 CTAs, one wave at 4 CTAs/SM. f32x2 dual chains from
// lane-duplicated smem Z. Stores: rows m < M_RESIDENT carry an
// L2::evict_last cache hint (policy-protected residency across graph
// replays -> those dirty lines are re-dirtied in place, never drained);
// all other rows stream with .cs (evict-first, cannot displace the
// resident set).
// ---------------------------------------------------------------------------
__global__ void __launch_bounds__(256, 4) main_kernel(
    const float* __restrict__ phi,       // (2, N)
    const float* __restrict__ pod,       // (N, 2)
    const float* __restrict__ omega,     // (6,)
    const float* __restrict__ c_coef,    // (6,)
    const float* __restrict__ z_values,  // (6, M)
    const float* __restrict__ zsin,      // (2, M)
    const float* __restrict__ zcos,      // (2, M)
    const float* __restrict__ ztanh,     // (2, M)
    const float* __restrict__ sin_coef,  // (2,)
    const float* __restrict__ cos_coef,  // (2,)
    const float* __restrict__ tanh_coef, // (2,)
    float* __restrict__ out) {
    __shared__ float s_z[24 * MC_MAX];   // lane-duplicated Z chunk, ~16 KB

    const int tid = threadIdx.x;
    const int y   = blockIdx.y;
    const int m0  = y * 166 + min(y, 4);
    const int mc  = 166 + (y < 4 ? 1 : 0);

    // build Z chunk in shared: 12 entries per m, each duplicated into a pair
    for (int m = tid; m < mc; m += 256) {
        const int gm = m0 + m;
        float v[12];
#pragma unroll
        for (int t = 0; t < 6; t++) v[t] = c_coef[t] * z_values[t * M_DIM + gm];
        v[6]  = sin_coef[0]  * zsin[gm];
        v[7]  = sin_coef[1]  * zsin[M_DIM + gm];
        v[8]  = cos_coef[0]  * zcos[gm];
        v[9]  = cos_coef[1]  * zcos[M_DIM + gm];
        v[10] = tanh_coef[0] * ztanh[gm];
        v[11] = tanh_coef[1] * ztanh[M_DIM + gm];
#pragma unroll
        for (int k = 0; k < 12; k++) {
            s_z[m * 24 + 2 * k]     = v[k];
            s_z[m * 24 + 2 * k + 1] = v[k];
        }
    }

    // one CTA copies the third output (z_values verbatim, 6*M floats)
    if (blockIdx.x == 0 && y == 0) {
        float* ztail = out + (size_t)M_DIM * N_DIM + 2 * (size_t)N_DIM;
        for (int i = tid; i < 6 * M_DIM; i += 256) ztail[i] = z_values[i];
    }

    const int n0 = blockIdx.x * NPB + tid * 4;
    __syncthreads();
    if (n0 >= N_DIM) return;   // N % 4 == 0: groups all-in or all-out

    // evict_last residency policy (fraction 1.0)
    unsigned long long pol;
    asm("createpolicy.fractional.L2::evict_last.b64 %0, 1.0;" : "=l"(pol));

    const float om0 = omega[0], om1 = omega[1], om2 = omega[2];
    const float om3 = omega[3], om4 = omega[4], om5 = omega[5];

    float ps0[4], ps1[4];
#pragma unroll
    for (int j = 0; j < 4; j++) {
        const int n = n0 + j;
        ps0[j] = phi[n]         * pod[2 * n];
        ps1[j] = phi[N_DIM + n] * pod[2 * n + 1];
    }

    // second output: latent_spatial (N,2), write once (m-chunk 0 only)
    if (y == 0) {
        float* lat = out + (size_t)M_DIM * N_DIM + 2 * (size_t)n0;
        *(float4*)(lat)     = make_float4(ps0[0], ps1[0], ps0[1], ps1[1]);
        *(float4*)(lat + 4) = make_float4(ps0[2], ps1[2], ps0[3], ps1[3]);
    }

    // W vector components k = 1..11 (k=0 is the constant-1 term)
    float w[12][4];
#pragma unroll
    for (int j = 0; j < 4; j++) {
        const float y0 = ps0[j], y1 = ps1[j];
        w[1][j]  = y0;
        w[2][j]  = y1;
        w[3][j]  = y0 * y0;
        w[4][j]  = y0 * y1;
        w[5][j]  = y1 * y1;
        w[6][j]  = sinf(om0 * y0);
        w[7][j]  = sinf(om3 * y1);
        w[8][j]  = cosf(om1 * y0);
        w[9][j]  = cosf(om4 * y1);
        w[10][j] = tanhf(om2 * y0);
        w[11][j] = tanhf(om5 * y1);
    }

    unsigned long long wa[11], wb[11];
#pragma unroll
    for (int k = 1; k < 12; k++) {
        wa[k - 1] = pk2(w[k][0], w[k][1]);
        wb[k - 1] = pk2(w[k][2], w[k][3]);
    }

    float* outbase = out + (size_t)m0 * N_DIM + n0;
    const ulonglong2* zp = (const ulonglong2*)s_z;  // 6 x ulonglong2 per m

#pragma unroll 4
    for (int mm = 0; mm < mc; mm++) {
        const ulonglong2* row = zp + mm * 6;
        const ulonglong2 z01 = row[0], z23 = row[1], z45 = row[2];
        const ulonglong2 z67 = row[3], z89 = row[4], zAB = row[5];

        // two independent 11-deep fma2 chains; k=0 term (W = 1) seeds each
        unsigned long long a0 = z01.x, a1 = z01.x;
        fma2(a0, wa[0],  z01.y, a0);  fma2(a1, wb[0],  z01.y, a1);
        fma2(a0, wa[1],  z23.x, a0);  fma2(a1, wb[1],  z23.x, a1);
        fma2(a0, wa[2],  z23.y, a0);  fma2(a1, wb[2],  z23.y, a1);
        fma2(a0, wa[3],  z45.x, a0);  fma2(a1, wb[3],  z45.x, a1);
        fma2(a0, wa[4],  z45.y, a0);  fma2(a1, wb[4],  z45.y, a1);
        fma2(a0, wa[5],  z67.x, a0);  fma2(a1, wb[5],  z67.x, a1);
        fma2(a0, wa[6],  z67.y, a0);  fma2(a1, wb[6],  z67.y, a1);
        fma2(a0, wa[7],  z89.x, a0);  fma2(a1, wb[7],  z89.x, a1);
        fma2(a0, wa[8],  z89.y, a0);  fma2(a1, wb[8],  z89.y, a1);
        fma2(a0, wa[9],  zAB.x, a0);  fma2(a1, wb[9],  zAB.x, a1);
        fma2(a0, wa[10], zAB.y, a0);  fma2(a1, wb[10], zAB.y, a1);

        float* p = outbase + (size_t)mm * N_DIM;
        if (m0 + mm < M_RESIDENT) stel4(p, a0, a1, pol);  // resident slice
        else                      stcs4(p, a0, a1);       // streaming slice
    }
}

extern "C" void kernel_launch(void* const* d_in, const int* in_sizes, int n_in,
                              void* d_out, int out_size) {
    // metadata order:
    // 0:X 1:phi 2:POD_modes 3:c_coef 4:z_values 5:zsin 6:zcos 7:ztanh
    // 8:sin_coef 9:cos_coef 10:tanh_coef 11:omega
    const float* phi       = (const float*)d_in[1];
    const float* pod       = (const float*)d_in[2];
    const float* c_coef    = (const float*)d_in[3];
    const float* z_values  = (const float*)d_in[4];
    const float* zsin      = (const float*)d_in[5];
    const float* zcos      = (const float*)d_in[6];
    const float* ztanh     = (const float*)d_in[7];
    const float* sin_coef  = (const float*)d_in[8];
    const float* cos_coef  = (const float*)d_in[9];
    const float* tanh_coef = (const float*)d_in[10];
    const float* omega     = (const float*)d_in[11];

    float* out = (float*)d_out;

    dim3 grid((N_DIM + NPB - 1) / NPB, 6);  // (98, 6) = 588 CTAs = one wave
    main_kernel<<<grid, 256>>>(phi, pod, omega, c_coef, z_values, zsin, zcos,
                               ztanh, sin_coef, cos_coef, tanh_coef, out);
}

// round 17
// speedup vs baseline: 1.0449x; 1.0449x over previous
#include <cuda_runtime.h>

#define M_DIM 1000
#define N_DIM 100000
#define NPB 1024            // n per block: 256 threads * 4
#define MC_MAX 167          // max m per block (grid.y = 6)

__device__ __forceinline__ unsigned long long pk2(float lo, float hi) {
    unsigned long long r;
    asm("mov.b64 %0, {%1, %2};" : "=l"(r) : "f"(lo), "f"(hi));
    return r;
}

__device__ __forceinline__ void fma2(unsigned long long& d,
                                     unsigned long long a,
                                     unsigned long long b,
                                     unsigned long long c) {
    asm("fma.rn.f32x2 %0, %1, %2, %3;" : "=l"(d) : "l"(a), "l"(b), "l"(c));
}

__device__ __forceinline__ void stcs4(float* p, unsigned long long a,
                                      unsigned long long b) {
    float x, y, z, w;
    asm("mov.b64 {%0, %1}, %2;" : "=f"(x), "=f"(y) : "l"(a));
    asm("mov.b64 {%0, %1}, %2;" : "=f"(z), "=f"(w) : "l"(b));
    asm volatile("st.global.cs.v4.f32 [%0], {%1, %2, %3, %4};"
                 :: "l"(p), "f"(x), "f"(y), "f"(z), "f"(w) : "memory");
}

__device__ __forceinline__ void sts4(unsigned int saddr, unsigned long long a,
                                     unsigned long long b) {
    float x, y, z, w;
    asm("mov.b64 {%0, %1}, %2;" : "=f"(x), "=f"(y) : "l"(a));
    asm("mov.b64 {%0, %1}, %2;" : "=f"(z), "=f"(w) : "l"(b));
    asm volatile("st.shared.v4.f32 [%0], {%1, %2, %3, %4};"
                 :: "r"(saddr), "f"(x), "f"(y), "f"(z), "f"(w) : "memory");
}

__device__ __forceinline__ unsigned int smem_u32(const void* p) {
    unsigned int a;
    asm("{ .reg .u64 t; cvta.to.shared.u64 t, %1; cvt.u32.u64 %0, t; }"
        : "=r"(a) : "l"(p));
    return a;
}

// ---------------------------------------------------------------------------
// Fused kernel, DUAL write path (validated R10/R12/R14/R15 configuration):
// even m-rows store directly via LSU (st.global.cs); odd m-rows stage in a
// 3-deep smem ring and go out via the TMA engine (cp.async.bulk).
// grid (98,6) = 588 CTAs, 4 CTAs/SM, one wave.
// ---------------------------------------------------------------------------
__global__ void __launch_bounds__(256, 4) main_kernel(
    const float* __restrict__ phi,       // (2, N)
    const float* __restrict__ pod,       // (N, 2)
    const float* __restrict__ omega,     // (6,)
    const float* __restrict__ c_coef,    // (6,)
    const float* __restrict__ z_values,  // (6, M)
    const float* __restrict__ zsin,      // (2, M)
    const float* __restrict__ zcos,      // (2, M)
    const float* __restrict__ ztanh,     // (2, M)
    const float* __restrict__ sin_coef,  // (2,)
    const float* __restrict__ cos_coef,  // (2,)
    const float* __restrict__ tanh_coef, // (2,)
    float* __restrict__ out) {
    __shared__ float s_z[24 * MC_MAX];               // dup Z chunk, ~16 KB
    __shared__ __align__(16) float s_out[3][NPB];    // TMA staging ring, 12 KB

    const int tid = threadIdx.x;
    const int y   = blockIdx.y;
    const int bx  = blockIdx.x;
    const int m0  = y * 166 + min(y, 4);
    const int mc  = 166 + (y < 4 ? 1 : 0);

    // build Z chunk in shared: 12 entries per m, each duplicated into a pair
    for (int m = tid; m < mc; m += 256) {
        const int gm = m0 + m;
        float v[12];
#pragma unroll
        for (int t = 0; t < 6; t++) v[t] = c_coef[t] * z_values[t * M_DIM + gm];
        v[6]  = sin_coef[0]  * zsin[gm];
        v[7]  = sin_coef[1]  * zsin[M_DIM + gm];
        v[8]  = cos_coef[0]  * zcos[gm];
        v[9]  = cos_coef[1]  * zcos[M_DIM + gm];
        v[10] = tanh_coef[0] * ztanh[gm];
        v[11] = tanh_coef[1] * ztanh[M_DIM + gm];
#pragma unroll
        for (int k = 0; k < 12; k++) {
            s_z[m * 24 + 2 * k]     = v[k];
            s_z[m * 24 + 2 * k + 1] = v[k];
        }
    }

    // one CTA copies the third output (z_values verbatim, 6*M floats)
    if (bx == 0 && y == 0) {
        float* ztail = out + (size_t)M_DIM * N_DIM + 2 * (size_t)N_DIM;
        for (int i = tid; i < 6 * M_DIM; i += 256) ztail[i] = z_values[i];
    }

    const int n0 = bx * NPB + tid * 4;
    const bool active = (n0 < N_DIM);   // N % 4 == 0: group all-in or all-out
    const int nsafe = active ? n0 : 0;

    const float om0 = omega[0], om1 = omega[1], om2 = omega[2];
    const float om3 = omega[3], om4 = omega[4], om5 = omega[5];

    float ps0[4], ps1[4];
#pragma unroll
    for (int j = 0; j < 4; j++) {
        const int n = nsafe + j;
        ps0[j] = phi[n]         * pod[2 * n];
        ps1[j] = phi[N_DIM + n] * pod[2 * n + 1];
    }

    // second output: latent_spatial (N,2), write once (m-chunk 0 only)
    if (y == 0 && active) {
        float* lat = out + (size_t)M_DIM * N_DIM + 2 * (size_t)n0;
        *(float4*)(lat)     = make_float4(ps0[0], ps1[0], ps0[1], ps1[1]);
        *(float4*)(lat + 4) = make_float4(ps0[2], ps1[2], ps0[3], ps1[3]);
    }

    // W vector components k = 1..11 (k=0 is the constant-1 term)
    float w[12][4];
#pragma unroll
    for (int j = 0; j < 4; j++) {
        const float y0 = ps0[j], y1 = ps1[j];
        w[1][j]  = y0;
        w[2][j]  = y1;
        w[3][j]  = y0 * y0;
        w[4][j]  = y0 * y1;
        w[5][j]  = y1 * y1;
        w[6][j]  = sinf(om0 * y0);
        w[7][j]  = sinf(om3 * y1);
        w[8][j]  = cosf(om1 * y0);
        w[9][j]  = cosf(om4 * y1);
        w[10][j] = tanhf(om2 * y0);
        w[11][j] = tanhf(om5 * y1);
    }

    unsigned long long wa[11], wb[11];
#pragma unroll
    for (int k = 1; k < 12; k++) {
        wa[k - 1] = pk2(w[k][0], w[k][1]);
        wb[k - 1] = pk2(w[k][2], w[k][3]);
    }

    const int nblk0 = bx * NPB;
    const unsigned int tile_bytes =
        (unsigned int)(min(NPB, N_DIM - nblk0) * 4);   // 4096 or 2688 (bx=97)
    float* dst0 = out + (size_t)m0 * N_DIM + nblk0;
    const unsigned int s_stage = smem_u32(&s_out[0][0]);
    const unsigned int s_mine  = s_stage + (unsigned int)(tid * 16);

    float* outbase = out + (size_t)m0 * N_DIM + n0;
    const ulonglong2* zp = (const ulonglong2*)s_z;  // 6 x ulonglong2 per m
    __syncthreads();                                // s_z ready

    for (int mm = 0; mm < mc; mm++) {
        const bool tma_row = (mm & 1);
        const unsigned int bufoff =
            (unsigned int)((mm >> 1) % 3) * (NPB * 4);

        if (active) {
            const ulonglong2* row = zp + mm * 6;
            const ulonglong2 z01 = row[0], z23 = row[1], z45 = row[2];
            const ulonglong2 z67 = row[3], z89 = row[4], zAB = row[5];

            unsigned long long a0 = z01.x, a1 = z01.x;  // k=0 seeds (W = 1)
            fma2(a0, wa[0],  z01.y, a0);  fma2(a1, wb[0],  z01.y, a1);
            fma2(a0, wa[1],  z23.x, a0);  fma2(a1, wb[1],  z23.x, a1);
            fma2(a0, wa[2],  z23.y, a0);  fma2(a1, wb[2],  z23.y, a1);
            fma2(a0, wa[3],  z45.x, a0);  fma2(a1, wb[3],  z45.x, a1);
            fma2(a0, wa[4],  z45.y, a0);  fma2(a1, wb[4],  z45.y, a1);
            fma2(a0, wa[5],  z67.x, a0);  fma2(a1, wb[5],  z67.x, a1);
            fma2(a0, wa[6],  z67.y, a0);  fma2(a1, wb[6],  z67.y, a1);
            fma2(a0, wa[7],  z89.x, a0);  fma2(a1, wb[7],  z89.x, a1);
            fma2(a0, wa[8],  z89.y, a0);  fma2(a1, wb[8],  z89.y, a1);
            fma2(a0, wa[9],  zAB.x, a0);  fma2(a1, wb[9],  zAB.x, a1);
            fma2(a0, wa[10], zAB.y, a0);  fma2(a1, wb[10], zAB.y, a1);

            if (tma_row) sts4(s_mine + bufoff, a0, a1);
            else         stcs4(outbase + (size_t)mm * N_DIM, a0, a1);
        }

        if (tma_row) {
            __syncthreads();   // staging tile complete
            if (tid == 0) {
                asm volatile("fence.proxy.async.shared::cta;" ::: "memory");
                asm volatile(
                    "cp.async.bulk.global.shared::cta.bulk_group [%0], [%1], %2;"
                    :: "l"(dst0 + (size_t)mm * N_DIM), "r"(s_stage + bufoff),
                       "r"(tile_bytes) : "memory");
                asm volatile("cp.async.bulk.commit_group;" ::: "memory");
                // <=2 groups in flight; 3rd buffer becomes reusable
                asm volatile("cp.async.bulk.wait_group.read 2;" ::: "memory");
            }
            __syncthreads();   // buffer-reuse release
        }
    }

    if (tid == 0)
        asm volatile("cp.async.bulk.wait_group 0;" ::: "memory");
}

extern "C" void kernel_launch(void* const* d_in, const int* in_sizes, int n_in,
                              void* d_out, int out_size) {
    // metadata order:
    // 0:X 1:phi 2:POD_modes 3:c_coef 4:z_values 5:zsin 6:zcos 7:ztanh
    // 8:sin_coef 9:cos_coef 10:tanh_coef 11:omega
    const float* phi       = (const float*)d_in[1];
    const float* pod       = (const float*)d_in[2];
    const float* c_coef    = (const float*)d_in[3];
    const float* z_values  = (const float*)d_in[4];
    const float* zsin      = (const float*)d_in[5];
    const float* zcos      = (const float*)d_in[6];
    const float* ztanh     = (const float*)d_in[7];
    const float* sin_coef  = (const float*)d_in[8];
    const float* cos_coef  = (const float*)d_in[9];
    const float* tanh_coef = (const float*)d_in[10];
    const float* omega     = (const float*)d_in[11];

    float* out = (float*)d_out;

    dim3 grid((N_DIM + NPB - 1) / NPB, 6);  // (98, 6) = 588 CTAs = one wave
    main_kernel<<<grid, 256>>>(phi, pod, omega, c_coef, z_values, zsin, zcos,
                               ztanh, sin_coef, cos_coef, tanh_coef, out);
}